// round 11
// baseline (speedup 1.0000x reference)
#include <cuda_runtime.h>
#include <cuda_bf16.h>

// HashNGramEmbedder — single fused kernel.
// out[b,s,:] = ( main_w[tok] + sum_{n=3..8} shared_w[idx_n] + sum_n size_w[n-3] ) / 7
// idx_n = ( sum_{j=0}^{n-1} tok[s-j] * 260^j mod 2^23 ) mod 500000, or 0 if s < n-1.
//
// Per-warp 8-lane shfl prefix scan computes all 6 hashes, no barrier / no smem.
// shared_w gathers carry an L2 evict-last policy (createpolicy + cache_hint —
// the only PTX-legal route for 16B loads on sm_103a); the output store is
// evict-first (__stcs). Net: duplicate bucket rows (~17% of gathers) stay
// L2-resident longer.
//
// Shapes (metadata order):
//   d_in[0] tokens   int32  [4, 8192]
//   d_in[1] main_w   f32    [259, 512]
//   d_in[2] shared_w f32    [500000, 512]
//   d_in[3] size_w   f32    [6, 512]
//   d_out            f32    [4, 8192, 512]

#define EMBED_D     512
#define DV          (EMBED_D / 4)      // 128 float4 lanes per row
#define SEQ_LEN     8192
#define N_BATCH     4
#define N_POS       (N_BATCH * SEQ_LEN)
#define HASH_MASK   ((1u << 23) - 1u)
#define N_BUCKETS   500000
#define INV_CONTRIB (1.0f / 7.0f)

// 260^j mod 2^23, j = 0..7
__constant__ unsigned c_pw[8] = {
    1u, 260u, 67600u, 798784u, 6357248u, 328704u, 1576960u, 7356416u
};

__device__ __forceinline__ float4 ldg_el(const float4* p, unsigned long long pol)
{
    float4 r;
    asm("ld.global.nc.L2::cache_hint.v4.f32 {%0,%1,%2,%3}, [%4], %5;"
        : "=f"(r.x), "=f"(r.y), "=f"(r.z), "=f"(r.w)
        : "l"(p), "l"(pol));
    return r;
}

__global__ __launch_bounds__(DV, 12)
void hashngram_fused_kernel(const int*    __restrict__ tokens,
                            const float4* __restrict__ main_w,
                            const float4* __restrict__ shared_w,
                            const float4* __restrict__ size_w,
                            float4*       __restrict__ out)
{
    const int pos  = blockIdx.x;           // b * SEQ_LEN + s
    const int s    = pos & (SEQ_LEN - 1);
    const int* t   = tokens + (pos - s);   // batch-row base
    const int k    = (int)threadIdx.x & 7; // lane position within 8-lane hash group

    // L2 evict-last policy descriptor (uniform).
    unsigned long long pol;
    asm("createpolicy.fractional.L2::evict_last.b64 %0, 1.0;" : "=l"(pol));

    // ---- per-warp hash via 8-lane shfl prefix scan ----
    const int tk = (k <= s) ? t[s - k] : 0;              // 8 consecutive ints
    unsigned v = ((unsigned)tk * c_pw[k]) & HASH_MASK;   // term_k

    unsigned u;
    u = __shfl_up_sync(0xffffffffu, v, 1, 8); if (k >= 1) v += u;
    u = __shfl_up_sync(0xffffffffu, v, 2, 8); if (k >= 2) v += u;
    u = __shfl_up_sync(0xffffffffu, v, 4, 8); if (k >= 4) v += u;
    // lane k: P_k = sum_{j<=k} term_j  (< 2^26, no overflow)

    int idx = (s >= k) ? (int)((v & HASH_MASK) % N_BUCKETS) : 0;

    const int tok = __shfl_sync(0xffffffffu, tk, 0);     // t[s]
    const int i3  = __shfl_sync(0xffffffffu, idx, 2);    // n = 3..8
    const int i4  = __shfl_sync(0xffffffffu, idx, 3);
    const int i5  = __shfl_sync(0xffffffffu, idx, 4);
    const int i6  = __shfl_sync(0xffffffffu, idx, 5);
    const int i7  = __shfl_sync(0xffffffffu, idx, 6);
    const int i8  = __shfl_sync(0xffffffffu, idx, 7);

    // ---- 7 independent row gathers (the DRAM traffic) ----
    const int d = (int)threadIdx.x;        // float4 lane within the 512-wide row
    float4 m  = __ldg(&main_w[(size_t)tok * DV + d]);    // 530 KB table, L2-hot
    float4 g0 = ldg_el(&shared_w[(size_t)i3 * DV + d], pol);
    float4 g1 = ldg_el(&shared_w[(size_t)i4 * DV + d], pol);
    float4 g2 = ldg_el(&shared_w[(size_t)i5 * DV + d], pol);
    float4 g3 = ldg_el(&shared_w[(size_t)i6 * DV + d], pol);
    float4 g4 = ldg_el(&shared_w[(size_t)i7 * DV + d], pol);
    float4 g5 = ldg_el(&shared_w[(size_t)i8 * DV + d], pol);

    float4 acc;
    acc.x = m.x + g0.x + g1.x + g2.x + g3.x + g4.x + g5.x;
    acc.y = m.y + g0.y + g1.y + g2.y + g3.y + g4.y + g5.y;
    acc.z = m.z + g0.z + g1.z + g2.z + g3.z + g4.z + g5.z;
    acc.w = m.w + g0.w + g1.w + g2.w + g3.w + g4.w + g5.w;

    // size_w: 12 KB, L1/L2 resident; folded after the gathers so its temps
    // stay cold (short-lived) under the register cap.
    #pragma unroll
    for (int n = 0; n < 6; n++) {
        float4 z = __ldg(&size_w[n * DV + d]);
        acc.x += z.x; acc.y += z.y; acc.z += z.z; acc.w += z.w;
    }

    acc.x *= INV_CONTRIB;
    acc.y *= INV_CONTRIB;
    acc.z *= INV_CONTRIB;
    acc.w *= INV_CONTRIB;

    // Streaming (evict-first) store: the 64 MB output must not displace the
    // evict-last shared_w rows.
    __stcs(&out[(size_t)pos * DV + d], acc);
}

extern "C" void kernel_launch(void* const* d_in, const int* in_sizes, int n_in,
                              void* d_out, int out_size)
{
    const int*    tokens   = (const int*)d_in[0];
    const float4* main_w   = (const float4*)d_in[1];
    const float4* shared_w = (const float4*)d_in[2];
    const float4* size_w   = (const float4*)d_in[3];
    float4*       out      = (float4*)d_out;

    hashngram_fused_kernel<<<N_POS, DV>>>(tokens, main_w, shared_w, size_w, out);
}